// round 3
// baseline (speedup 1.0000x reference)
#include <cuda_runtime.h>
#include <cstdint>

#define NN 50000
#define EE 800000
#define KD 128      // IN_C == HID_C
#define OC 64       // OUT_C

// ---------------- scratch (device globals; no allocation allowed) ----------
__device__ __align__(16) float g_H1[NN * KD];   // X*W1^T + b1
__device__ __align__(16) float g_A1[NN * KD];   // layer-1 aggregated (pre-relu)
__device__ __align__(16) float g_H2[NN * OC];   // relu(A1)*W2^T + b2
__device__ int   g_deg1[NN], g_deg2[NN];
__device__ int   g_off1[NN], g_off2[NN];
__device__ int   g_cur1[NN], g_cur2[NN];
__device__ int   g_csr1[EE], g_csr2[EE];
__device__ float g_norm1[NN], g_norm2[NN];
__device__ int   g_tot1, g_tot2;

// ---------------- f32x2 helpers (Blackwell packed fp32) ---------------------
__device__ __forceinline__ unsigned long long pk2(float lo, float hi) {
    unsigned long long r;
    asm("mov.b64 %0, {%1, %2};" : "=l"(r) : "f"(lo), "f"(hi));
    return r;
}
__device__ __forceinline__ void up2(unsigned long long v, float& lo, float& hi) {
    asm("mov.b64 {%0, %1}, %2;" : "=f"(lo), "=f"(hi) : "l"(v));
}
__device__ __forceinline__ void ffma2(unsigned long long& d,
                                      unsigned long long a, unsigned long long b) {
    asm("fma.rn.f32x2 %0, %1, %2, %0;" : "+l"(d) : "l"(a), "l"(b));
}

// ---------------- init / degree / offsets / fill ----------------------------
__global__ void k_init() {
    int i = blockIdx.x * blockDim.x + threadIdx.x;
    if (i < NN) { g_deg1[i] = 0; g_deg2[i] = 0; }
    if (i == 0) { g_tot1 = 0; g_tot2 = 0; }
}

// 4 edges per thread, int4 loads, no-return atomics (REDG)
__global__ __launch_bounds__(256) void k_count(const int* __restrict__ ei) {
    int t = blockIdx.x * blockDim.x + threadIdx.x;        // t in [0, EE/4)
    if (t >= EE / 4) return;
    int4 r4 = ((const int4*)ei)[t];
    int4 c4 = ((const int4*)(ei + EE))[t];
    atomicAdd(&g_deg1[c4.x], 1);
    atomicAdd(&g_deg1[c4.y], 1);
    atomicAdd(&g_deg1[c4.z], 1);
    atomicAdd(&g_deg1[c4.w], 1);
    atomicAdd(&g_deg2[r4.x], 1);
    atomicAdd(&g_deg2[r4.y], 1);
    atomicAdd(&g_deg2[r4.z], 1);
    atomicAdd(&g_deg2[r4.w], 1);
}

// block-wide exclusive scan of degrees -> CSR offsets + cursors + norms
__global__ __launch_bounds__(256) void k_offsets() {
    int v = blockIdx.x * 256 + threadIdx.x;
    int lane = threadIdx.x & 31, w = threadIdx.x >> 5;
    int d1 = (v < NN) ? g_deg1[v] : 0;
    int d2 = (v < NN) ? g_deg2[v] : 0;
    int x1 = d1, x2 = d2;
#pragma unroll
    for (int o = 1; o < 32; o <<= 1) {
        int y1 = __shfl_up_sync(0xffffffffu, x1, o);
        int y2 = __shfl_up_sync(0xffffffffu, x2, o);
        if (lane >= o) { x1 += y1; x2 += y2; }
    }
    __shared__ int ws1[8], ws2[8], sbase[2];
    if (lane == 31) { ws1[w] = x1; ws2[w] = x2; }
    __syncthreads();
    int pre1 = 0, tot1 = 0, pre2 = 0, tot2 = 0;
#pragma unroll
    for (int i = 0; i < 8; i++) {
        int a = ws1[i], b = ws2[i];
        if (i < w) { pre1 += a; pre2 += b; }
        tot1 += a; tot2 += b;
    }
    if (threadIdx.x == 0) {
        sbase[0] = atomicAdd(&g_tot1, tot1);
        sbase[1] = atomicAdd(&g_tot2, tot2);
    }
    __syncthreads();
    if (v < NN) {
        int o1 = sbase[0] + pre1 + (x1 - d1);
        int o2 = sbase[1] + pre2 + (x2 - d2);
        g_off1[v] = o1; g_cur1[v] = o1;
        g_off2[v] = o2; g_cur2[v] = o2;
        g_norm1[v] = 1.0f / (float)(d1 + 1);   // +1 self loop
        g_norm2[v] = 1.0f / (float)(d2 + 1);
    }
}

// 4 edges per thread: 8 independent atomic+store chains in flight
__global__ __launch_bounds__(256) void k_fill(const int* __restrict__ ei) {
    int t = blockIdx.x * blockDim.x + threadIdx.x;
    if (t >= EE / 4) return;
    int4 r4 = ((const int4*)ei)[t];
    int4 c4 = ((const int4*)(ei + EE))[t];
    int p10 = atomicAdd(&g_cur1[c4.x], 1);
    int p11 = atomicAdd(&g_cur1[c4.y], 1);
    int p12 = atomicAdd(&g_cur1[c4.z], 1);
    int p13 = atomicAdd(&g_cur1[c4.w], 1);
    int p20 = atomicAdd(&g_cur2[r4.x], 1);
    int p21 = atomicAdd(&g_cur2[r4.y], 1);
    int p22 = atomicAdd(&g_cur2[r4.z], 1);
    int p23 = atomicAdd(&g_cur2[r4.w], 1);
    g_csr1[p10] = r4.x;  g_csr1[p11] = r4.y;
    g_csr1[p12] = r4.z;  g_csr1[p13] = r4.w;
    g_csr2[p20] = c4.x;  g_csr2[p21] = c4.y;
    g_csr2[p22] = c4.z;  g_csr2[p23] = c4.w;
}

// ---------------- GEMM: C[M,BN] = A[M,128]*W[BN,128]^T + bias  (f32x2) ------
template<int BN, bool RELU>
__global__ __launch_bounds__(256, 1)
void k_gemm(const float* __restrict__ A, const float* __restrict__ W,
            const float* __restrict__ bias, float* __restrict__ C, int M) {
    constexpr int TN = BN / 16;
    extern __shared__ float sm[];
    float* As = sm;              // 128*128
    float* Bs = sm + 128 * 128;  // 128*BN
    const int tid = threadIdx.x;
    const int tx = tid & 15, ty = tid >> 4;
    const int m0 = blockIdx.x * 128;

    for (int idx = tid; idx < 128 * 32; idx += 256) {
        int m = idx >> 5, f = idx & 31;
        float4 v = make_float4(0.f, 0.f, 0.f, 0.f);
        int gm = m0 + m;
        if (gm < M) v = *(const float4*)(A + (size_t)gm * KD + f * 4);
        if (RELU) {
            v.x = fmaxf(v.x, 0.f); v.y = fmaxf(v.y, 0.f);
            v.z = fmaxf(v.z, 0.f); v.w = fmaxf(v.w, 0.f);
        }
        *(float4*)(As + m * 128 + f * 4) = v;
    }
    for (int idx = tid; idx < BN * 32; idx += 256) {
        int n = idx & (BN - 1);
        int f = idx / BN;
        float4 v = *(const float4*)(W + (size_t)n * KD + f * 4);
        Bs[(f * 4 + 0) * BN + n] = v.x;
        Bs[(f * 4 + 1) * BN + n] = v.y;
        Bs[(f * 4 + 2) * BN + n] = v.z;
        Bs[(f * 4 + 3) * BN + n] = v.w;
    }
    __syncthreads();

    unsigned long long acc[4][TN];
#pragma unroll
    for (int i = 0; i < 4; i++)
#pragma unroll
        for (int j = 0; j < TN; j++) acc[i][j] = 0ULL;

#pragma unroll 4
    for (int kk = 0; kk < 128; kk++) {
        const float* ar = As + (ty * 8) * 128 + kk;
        unsigned long long ap[4];
#pragma unroll
        for (int i = 0; i < 4; i++)
            ap[i] = pk2(ar[(2 * i) * 128], ar[(2 * i + 1) * 128]);
        unsigned long long bd[TN];
        {
            float4 b0 = *(const float4*)(Bs + kk * BN + tx * TN);
            bd[0] = pk2(b0.x, b0.x); bd[1] = pk2(b0.y, b0.y);
            bd[2] = pk2(b0.z, b0.z); bd[3] = pk2(b0.w, b0.w);
            if (TN == 8) {
                float4 b1 = *(const float4*)(Bs + kk * BN + tx * TN + 4);
                bd[4] = pk2(b1.x, b1.x); bd[5] = pk2(b1.y, b1.y);
                bd[6] = pk2(b1.z, b1.z); bd[7] = pk2(b1.w, b1.w);
            }
        }
#pragma unroll
        for (int i = 0; i < 4; i++)
#pragma unroll
            for (int j = 0; j < TN; j++)
                ffma2(acc[i][j], ap[i], bd[j]);
    }

    float bj[TN];
#pragma unroll
    for (int j = 0; j < TN; j++) bj[j] = bias[tx * TN + j];

#pragma unroll
    for (int mp = 0; mp < 4; mp++) {
        float lo[TN], hi[TN];
#pragma unroll
        for (int j = 0; j < TN; j++) up2(acc[mp][j], lo[j], hi[j]);
        int r0 = m0 + ty * 8 + mp * 2;
        if (r0 < M) {
#pragma unroll
            for (int q = 0; q < TN / 4; q++) {
                float4 o;
                o.x = lo[q * 4 + 0] + bj[q * 4 + 0];
                o.y = lo[q * 4 + 1] + bj[q * 4 + 1];
                o.z = lo[q * 4 + 2] + bj[q * 4 + 2];
                o.w = lo[q * 4 + 3] + bj[q * 4 + 3];
                *(float4*)(C + (size_t)r0 * BN + tx * TN + q * 4) = o;
            }
        }
        if (r0 + 1 < M) {
#pragma unroll
            for (int q = 0; q < TN / 4; q++) {
                float4 o;
                o.x = hi[q * 4 + 0] + bj[q * 4 + 0];
                o.y = hi[q * 4 + 1] + bj[q * 4 + 1];
                o.z = hi[q * 4 + 2] + bj[q * 4 + 2];
                o.w = hi[q * 4 + 3] + bj[q * 4 + 3];
                *(float4*)(C + (size_t)(r0 + 1) * BN + tx * TN + q * 4) = o;
            }
        }
    }
}

// ---------------- CSR gather ------------------------------------------------
// layer 1: warp per node, 128 feats = 32 x float4, unroll-4 neighbors
__global__ __launch_bounds__(256) void k_gather1() {
    int v = blockIdx.x * 8 + (threadIdx.x >> 5);
    if (v >= NN) return;
    int lane = threadIdx.x & 31;
    const float4* __restrict__ H = (const float4*)g_H1;
    int deg = g_deg1[v];
    const int* __restrict__ src = g_csr1 + g_off1[v];
    float4 a0 = H[(size_t)v * 32 + lane];
    float4 a1 = make_float4(0.f, 0.f, 0.f, 0.f);
    float4 a2 = make_float4(0.f, 0.f, 0.f, 0.f);
    float4 a3 = make_float4(0.f, 0.f, 0.f, 0.f);
    int j = 0;
    while (j < deg) {
        int cnt = deg - j; if (cnt > 32) cnt = 32;
        int u = (lane < cnt) ? src[j + lane] : 0;
        int k = 0;
        for (; k + 4 <= cnt; k += 4) {
            int u0 = __shfl_sync(0xffffffffu, u, k);
            int u1 = __shfl_sync(0xffffffffu, u, k + 1);
            int u2 = __shfl_sync(0xffffffffu, u, k + 2);
            int u3 = __shfl_sync(0xffffffffu, u, k + 3);
            float4 x0 = H[(size_t)u0 * 32 + lane];
            float4 x1 = H[(size_t)u1 * 32 + lane];
            float4 x2 = H[(size_t)u2 * 32 + lane];
            float4 x3 = H[(size_t)u3 * 32 + lane];
            a0.x += x0.x; a0.y += x0.y; a0.z += x0.z; a0.w += x0.w;
            a1.x += x1.x; a1.y += x1.y; a1.z += x1.z; a1.w += x1.w;
            a2.x += x2.x; a2.y += x2.y; a2.z += x2.z; a2.w += x2.w;
            a3.x += x3.x; a3.y += x3.y; a3.z += x3.z; a3.w += x3.w;
        }
        for (; k < cnt; k++) {
            int u0 = __shfl_sync(0xffffffffu, u, k);
            float4 x0 = H[(size_t)u0 * 32 + lane];
            a0.x += x0.x; a0.y += x0.y; a0.z += x0.z; a0.w += x0.w;
        }
        j += cnt;
    }
    float n = g_norm1[v];
    float4 o;
    o.x = n * (a0.x + a1.x + a2.x + a3.x);
    o.y = n * (a0.y + a1.y + a2.y + a3.y);
    o.z = n * (a0.z + a1.z + a2.z + a3.z);
    o.w = n * (a0.w + a1.w + a2.w + a3.w);
    ((float4*)g_A1)[(size_t)v * 32 + lane] = o;
}

// layer 2: HALF-warp per node (64 feats = 16 lanes x float4), unroll-4
__global__ __launch_bounds__(256) void k_gather2(float* __restrict__ out) {
    int warp = blockIdx.x * 8 + (threadIdx.x >> 5);
    int lane = threadIdx.x & 31;
    int half = lane >> 4;            // 0/1: which node in this warp
    int l    = lane & 15;
    int v = warp * 2 + half;
    if (v >= NN) return;
    const float4* __restrict__ H = (const float4*)g_H2;
    int deg = g_deg2[v];
    const int* __restrict__ src = g_csr2 + g_off2[v];
    float4 a0 = H[(size_t)v * 16 + l];
    float4 a1 = make_float4(0.f, 0.f, 0.f, 0.f);
    float4 a2 = make_float4(0.f, 0.f, 0.f, 0.f);
    float4 a3 = make_float4(0.f, 0.f, 0.f, 0.f);
    int j = 0;
    while (j < deg) {
        int cnt = deg - j; if (cnt > 16) cnt = 16;
        int u = (l < cnt) ? src[j + l] : 0;
        int k = 0;
        for (; k + 4 <= cnt; k += 4) {
            int u0 = __shfl_sync(0xffffffffu, u, k,     16);
            int u1 = __shfl_sync(0xffffffffu, u, k + 1, 16);
            int u2 = __shfl_sync(0xffffffffu, u, k + 2, 16);
            int u3 = __shfl_sync(0xffffffffu, u, k + 3, 16);
            float4 x0 = H[(size_t)u0 * 16 + l];
            float4 x1 = H[(size_t)u1 * 16 + l];
            float4 x2 = H[(size_t)u2 * 16 + l];
            float4 x3 = H[(size_t)u3 * 16 + l];
            a0.x += x0.x; a0.y += x0.y; a0.z += x0.z; a0.w += x0.w;
            a1.x += x1.x; a1.y += x1.y; a1.z += x1.z; a1.w += x1.w;
            a2.x += x2.x; a2.y += x2.y; a2.z += x2.z; a2.w += x2.w;
            a3.x += x3.x; a3.y += x3.y; a3.z += x3.z; a3.w += x3.w;
        }
        for (; k < cnt; k++) {
            int u0 = __shfl_sync(0xffffffffu, u, k, 16);
            float4 x0 = H[(size_t)u0 * 16 + l];
            a0.x += x0.x; a0.y += x0.y; a0.z += x0.z; a0.w += x0.w;
        }
        j += cnt;
    }
    float n = g_norm2[v];
    float4 o;
    o.x = n * (a0.x + a1.x + a2.x + a3.x);
    o.y = n * (a0.y + a1.y + a2.y + a3.y);
    o.z = n * (a0.z + a1.z + a2.z + a3.z);
    o.w = n * (a0.w + a1.w + a2.w + a3.w);
    ((float4*)out)[(size_t)v * 16 + l] = o;
}

// ---------------- launch -----------------------------------------------------
extern "C" void kernel_launch(void* const* d_in, const int* in_sizes, int n_in,
                              void* d_out, int out_size) {
    const float* x  = (const float*)d_in[0];
    const int*   ei = (const int*)d_in[1];
    const float* W1 = (const float*)d_in[2];
    const float* b1 = (const float*)d_in[3];
    const float* W2 = (const float*)d_in[4];
    const float* b2 = (const float*)d_in[5];
    float* out = (float*)d_out;

    float *pH1, *pA1, *pH2;
    cudaGetSymbolAddress((void**)&pH1, g_H1);
    cudaGetSymbolAddress((void**)&pA1, g_A1);
    cudaGetSymbolAddress((void**)&pH2, g_H2);

    cudaFuncSetAttribute(k_gemm<128, false>,
                         cudaFuncAttributeMaxDynamicSharedMemorySize, 131072);
    cudaFuncSetAttribute(k_gemm<64, true>,
                         cudaFuncAttributeMaxDynamicSharedMemorySize, 98304);

    // graph preprocessing
    k_init<<<(NN + 255) / 256, 256>>>();
    k_count<<<(EE / 4 + 255) / 256, 256>>>(ei);
    k_offsets<<<(NN + 255) / 256, 256>>>();
    k_fill<<<(EE / 4 + 255) / 256, 256>>>(ei);

    // layer 1
    k_gemm<128, false><<<(NN + 127) / 128, 256, 131072>>>(x, W1, b1, pH1, NN);
    k_gather1<<<(NN + 7) / 8, 256>>>();

    // layer 2 (relu folded into GEMM input read)
    k_gemm<64, true><<<(NN + 127) / 128, 256, 98304>>>(pA1, W2, b2, pH2, NN);
    k_gather2<<<(NN + 15) / 16, 256>>>(out);
}

// round 4
// speedup vs baseline: 1.1430x; 1.1430x over previous
#include <cuda_runtime.h>
#include <cstdint>

#define NN 50000
#define EE 800000
#define KD 128      // IN_C == HID_C
#define OC 64       // OUT_C
#define CAP 96      // per-node CSR bucket capacity (deg ~ Poisson(16))

// ---------------- scratch (device globals; no allocation allowed) ----------
__device__ __align__(16) float g_H1[NN * KD];   // X*W1^T + b1
__device__ __align__(16) float g_A1[NN * KD];   // relu(aggregated layer-1)
__device__ __align__(16) float g_H2[NN * OC];   // A1*W2^T + b2
__device__ int g_cur1[NN], g_cur2[NN];
__device__ int g_csr1[NN * CAP], g_csr2[NN * CAP];

// ---------------- f32x2 helpers (Blackwell packed fp32) ---------------------
__device__ __forceinline__ unsigned long long pk2(float lo, float hi) {
    unsigned long long r;
    asm("mov.b64 %0, {%1, %2};" : "=l"(r) : "f"(lo), "f"(hi));
    return r;
}
__device__ __forceinline__ void up2(unsigned long long v, float& lo, float& hi) {
    asm("mov.b64 {%0, %1}, %2;" : "=f"(lo), "=f"(hi) : "l"(v));
}
__device__ __forceinline__ void ffma2(unsigned long long& d,
                                      unsigned long long a, unsigned long long b) {
    asm("fma.rn.f32x2 %0, %1, %2, %0;" : "+l"(d) : "l"(a), "l"(b));
}

// ---------------- bucket-CSR build ------------------------------------------
__global__ void k_init() {
    int i = blockIdx.x * blockDim.x + threadIdx.x;
    if (i < NN) { g_cur1[i] = i * CAP; g_cur2[i] = i * CAP; }
}

// one edge per thread (measured faster than 4/thread: atomic-serialization
// bound, needs coverage not per-thread MLP)
__global__ __launch_bounds__(256) void k_fill(const int* __restrict__ ei) {
    int e = blockIdx.x * blockDim.x + threadIdx.x;
    if (e >= EE) return;
    int r = ei[e], c = ei[EE + e];
    int p1 = atomicAdd(&g_cur1[c], 1);
    g_csr1[p1] = r;                       // layer1: dest=col gathers row
    int p2 = atomicAdd(&g_cur2[r], 1);
    g_csr2[p2] = c;                       // layer2 (flipped): dest=row gathers col
}

// ---------------- GEMM: C[M,BN] = A[M,128]*W[BN,128]^T + bias  (f32x2) ------
template<int BN>
__global__ __launch_bounds__(256, 1)
void k_gemm(const float* __restrict__ A, const float* __restrict__ W,
            const float* __restrict__ bias, float* __restrict__ C, int M) {
    constexpr int TN = BN / 16;
    extern __shared__ float sm[];
    float* As = sm;              // 128*128
    float* Bs = sm + 128 * 128;  // 128*BN
    const int tid = threadIdx.x;
    const int tx = tid & 15, ty = tid >> 4;
    const int m0 = blockIdx.x * 128;

    for (int idx = tid; idx < 128 * 32; idx += 256) {
        int m = idx >> 5, f = idx & 31;
        float4 v = make_float4(0.f, 0.f, 0.f, 0.f);
        int gm = m0 + m;
        if (gm < M) v = *(const float4*)(A + (size_t)gm * KD + f * 4);
        *(float4*)(As + m * 128 + f * 4) = v;
    }
    for (int idx = tid; idx < BN * 32; idx += 256) {
        int n = idx & (BN - 1);
        int f = idx / BN;
        float4 v = *(const float4*)(W + (size_t)n * KD + f * 4);
        Bs[(f * 4 + 0) * BN + n] = v.x;
        Bs[(f * 4 + 1) * BN + n] = v.y;
        Bs[(f * 4 + 2) * BN + n] = v.z;
        Bs[(f * 4 + 3) * BN + n] = v.w;
    }
    __syncthreads();

    unsigned long long acc[4][TN];
#pragma unroll
    for (int i = 0; i < 4; i++)
#pragma unroll
        for (int j = 0; j < TN; j++) acc[i][j] = 0ULL;

#pragma unroll 4
    for (int kk = 0; kk < 128; kk++) {
        const float* ar = As + (ty * 8) * 128 + kk;
        unsigned long long ap[4];
#pragma unroll
        for (int i = 0; i < 4; i++)
            ap[i] = pk2(ar[(2 * i) * 128], ar[(2 * i + 1) * 128]);
        unsigned long long bd[TN];
        {
            float4 b0 = *(const float4*)(Bs + kk * BN + tx * TN);
            bd[0] = pk2(b0.x, b0.x); bd[1] = pk2(b0.y, b0.y);
            bd[2] = pk2(b0.z, b0.z); bd[3] = pk2(b0.w, b0.w);
            if (TN == 8) {
                float4 b1 = *(const float4*)(Bs + kk * BN + tx * TN + 4);
                bd[4] = pk2(b1.x, b1.x); bd[5] = pk2(b1.y, b1.y);
                bd[6] = pk2(b1.z, b1.z); bd[7] = pk2(b1.w, b1.w);
            }
        }
#pragma unroll
        for (int i = 0; i < 4; i++)
#pragma unroll
            for (int j = 0; j < TN; j++)
                ffma2(acc[i][j], ap[i], bd[j]);
    }

    float bj[TN];
#pragma unroll
    for (int j = 0; j < TN; j++) bj[j] = bias[tx * TN + j];

#pragma unroll
    for (int mp = 0; mp < 4; mp++) {
        float lo[TN], hi[TN];
#pragma unroll
        for (int j = 0; j < TN; j++) up2(acc[mp][j], lo[j], hi[j]);
        int r0 = m0 + ty * 8 + mp * 2;
        if (r0 < M) {
#pragma unroll
            for (int q = 0; q < TN / 4; q++) {
                float4 o;
                o.x = lo[q * 4 + 0] + bj[q * 4 + 0];
                o.y = lo[q * 4 + 1] + bj[q * 4 + 1];
                o.z = lo[q * 4 + 2] + bj[q * 4 + 2];
                o.w = lo[q * 4 + 3] + bj[q * 4 + 3];
                *(float4*)(C + (size_t)r0 * BN + tx * TN + q * 4) = o;
            }
        }
        if (r0 + 1 < M) {
#pragma unroll
            for (int q = 0; q < TN / 4; q++) {
                float4 o;
                o.x = hi[q * 4 + 0] + bj[q * 4 + 0];
                o.y = hi[q * 4 + 1] + bj[q * 4 + 1];
                o.z = hi[q * 4 + 2] + bj[q * 4 + 2];
                o.w = hi[q * 4 + 3] + bj[q * 4 + 3];
                *(float4*)(C + (size_t)(r0 + 1) * BN + tx * TN + q * 4) = o;
            }
        }
    }
}

// ---------------- CSR gather (warp per node, unroll-2) ----------------------
// A1[v] = relu( 1/(deg+1) * (H1[v] + sum_{u} H1[u]) ),  128 feats
__global__ __launch_bounds__(256) void k_gather1() {
    int v = blockIdx.x * 8 + (threadIdx.x >> 5);
    if (v >= NN) return;
    int lane = threadIdx.x & 31;
    const float4* __restrict__ H = (const float4*)g_H1;
    int deg = g_cur1[v] - v * CAP;
    const int* __restrict__ src = g_csr1 + v * CAP;
    float4 a0 = H[(size_t)v * 32 + lane];
    float4 a1 = make_float4(0.f, 0.f, 0.f, 0.f);
    int j = 0;
    while (j < deg) {
        int cnt = deg - j; if (cnt > 32) cnt = 32;
        int u = (lane < cnt) ? src[j + lane] : 0;
        int k = 0;
        for (; k + 2 <= cnt; k += 2) {
            int u0 = __shfl_sync(0xffffffffu, u, k);
            int u1 = __shfl_sync(0xffffffffu, u, k + 1);
            float4 x0 = H[(size_t)u0 * 32 + lane];
            float4 x1 = H[(size_t)u1 * 32 + lane];
            a0.x += x0.x; a0.y += x0.y; a0.z += x0.z; a0.w += x0.w;
            a1.x += x1.x; a1.y += x1.y; a1.z += x1.z; a1.w += x1.w;
        }
        if (k < cnt) {
            int u0 = __shfl_sync(0xffffffffu, u, k);
            float4 x0 = H[(size_t)u0 * 32 + lane];
            a0.x += x0.x; a0.y += x0.y; a0.z += x0.z; a0.w += x0.w;
        }
        j += cnt;
    }
    float n = 1.0f / (float)(deg + 1);
    float4 o;
    o.x = fmaxf(n * (a0.x + a1.x), 0.f);
    o.y = fmaxf(n * (a0.y + a1.y), 0.f);
    o.z = fmaxf(n * (a0.z + a1.z), 0.f);
    o.w = fmaxf(n * (a0.w + a1.w), 0.f);
    ((float4*)g_A1)[(size_t)v * 32 + lane] = o;
}

// out[v] = 1/(deg+1) * (H2[v] + sum H2[u]),  64 feats = 32 x float2
__global__ __launch_bounds__(256) void k_gather2(float* __restrict__ out) {
    int v = blockIdx.x * 8 + (threadIdx.x >> 5);
    if (v >= NN) return;
    int lane = threadIdx.x & 31;
    const float2* __restrict__ H = (const float2*)g_H2;
    int deg = g_cur2[v] - v * CAP;
    const int* __restrict__ src = g_csr2 + v * CAP;
    float2 a0 = H[(size_t)v * 32 + lane];
    float2 a1 = make_float2(0.f, 0.f);
    int j = 0;
    while (j < deg) {
        int cnt = deg - j; if (cnt > 32) cnt = 32;
        int u = (lane < cnt) ? src[j + lane] : 0;
        int k = 0;
        for (; k + 2 <= cnt; k += 2) {
            int u0 = __shfl_sync(0xffffffffu, u, k);
            int u1 = __shfl_sync(0xffffffffu, u, k + 1);
            float2 x0 = H[(size_t)u0 * 32 + lane];
            float2 x1 = H[(size_t)u1 * 32 + lane];
            a0.x += x0.x; a0.y += x0.y;
            a1.x += x1.x; a1.y += x1.y;
        }
        if (k < cnt) {
            int u0 = __shfl_sync(0xffffffffu, u, k);
            float2 x0 = H[(size_t)u0 * 32 + lane];
            a0.x += x0.x; a0.y += x0.y;
        }
        j += cnt;
    }
    float n = 1.0f / (float)(deg + 1);
    float2 o;
    o.x = n * (a0.x + a1.x);
    o.y = n * (a0.y + a1.y);
    ((float2*)out)[(size_t)v * 32 + lane] = o;
}

// ---------------- launch -----------------------------------------------------
extern "C" void kernel_launch(void* const* d_in, const int* in_sizes, int n_in,
                              void* d_out, int out_size) {
    const float* x  = (const float*)d_in[0];
    const int*   ei = (const int*)d_in[1];
    const float* W1 = (const float*)d_in[2];
    const float* b1 = (const float*)d_in[3];
    const float* W2 = (const float*)d_in[4];
    const float* b2 = (const float*)d_in[5];
    float* out = (float*)d_out;

    float *pH1, *pA1, *pH2;
    cudaGetSymbolAddress((void**)&pH1, g_H1);
    cudaGetSymbolAddress((void**)&pA1, g_A1);
    cudaGetSymbolAddress((void**)&pH2, g_H2);

    cudaFuncSetAttribute(k_gemm<128>,
                         cudaFuncAttributeMaxDynamicSharedMemorySize, 131072);
    cudaFuncSetAttribute(k_gemm<64>,
                         cudaFuncAttributeMaxDynamicSharedMemorySize, 98304);

    // bucket-CSR build (no count/scan phase)
    k_init<<<(NN + 255) / 256, 256>>>();
    k_fill<<<(EE + 255) / 256, 256>>>(ei);

    // layer 1 (relu folded into gather1 output)
    k_gemm<128><<<(NN + 127) / 128, 256, 131072>>>(x, W1, b1, pH1, NN);
    k_gather1<<<(NN + 7) / 8, 256>>>();

    // layer 2
    k_gemm<64><<<(NN + 127) / 128, 256, 98304>>>(pA1, W2, b2, pH2, NN);
    k_gather2<<<(NN + 7) / 8, 256>>>(out);
}

// round 5
// speedup vs baseline: 1.2742x; 1.1148x over previous
#include <cuda_runtime.h>
#include <cuda_fp16.h>
#include <cstdint>

#define NN 50000
#define EE 800000
#define KD 128      // IN_C == HID_C
#define OC 64       // OUT_C
#define CAP 96      // per-node CSR bucket capacity (deg ~ Poisson(16))

// ---------------- scratch (device globals; no allocation allowed) ----------
__device__ __align__(16) __half g_H1h[NN * KD];  // fp16 X*W1^T+b1 (gather src)
__device__ __align__(16) float  g_A1[NN * KD];   // relu(aggregated) fp32
__device__ __align__(16) __half g_H2h[NN * OC];  // fp16 A1*W2^T+b2 (gather src)
__device__ int g_cur1[NN], g_cur2[NN];
__device__ int g_csr1[NN * CAP], g_csr2[NN * CAP];

// ---------------- f32x2 helpers (Blackwell packed fp32) ---------------------
__device__ __forceinline__ unsigned long long pk2(float lo, float hi) {
    unsigned long long r;
    asm("mov.b64 %0, {%1, %2};" : "=l"(r) : "f"(lo), "f"(hi));
    return r;
}
__device__ __forceinline__ void up2(unsigned long long v, float& lo, float& hi) {
    asm("mov.b64 {%0, %1}, %2;" : "=f"(lo), "=f"(hi) : "l"(v));
}
__device__ __forceinline__ void ffma2(unsigned long long& d,
                                      unsigned long long a, unsigned long long b) {
    asm("fma.rn.f32x2 %0, %1, %2, %0;" : "+l"(d) : "l"(a), "l"(b));
}

// ---------------- bucket-CSR build ------------------------------------------
__global__ void k_init() {
    int i = blockIdx.x * blockDim.x + threadIdx.x;
    if (i < NN) { g_cur1[i] = i * CAP; g_cur2[i] = i * CAP; }
}

__global__ __launch_bounds__(256) void k_fill(const int* __restrict__ ei) {
    int e = blockIdx.x * blockDim.x + threadIdx.x;
    if (e >= EE) return;
    int r = ei[e], c = ei[EE + e];
    int p1 = atomicAdd(&g_cur1[c], 1);
    g_csr1[p1] = r;
    int p2 = atomicAdd(&g_cur2[r], 1);
    g_csr2[p2] = c;
}

// ---------------- GEMM1: H1h[M,128] = fp16( X[M,128]*W1[128,128]^T + b1 ) ---
// BM=64 (96KB smem -> 2 CTAs/SM, 16 warps). tx=lane: 4 n-cols; ty=warp: 8 m-rows.
__global__ __launch_bounds__(256, 2)
void k_gemm1(const float* __restrict__ A, const float* __restrict__ W,
             const float* __restrict__ bias, __half* __restrict__ C) {
    extern __shared__ float sm[];
    float* As = sm;              // [64][128] row-major
    float* Bs = sm + 64 * 128;   // [128 k][128 n]
    const int tid = threadIdx.x;
    const int tx = tid & 31, ty = tid >> 5;
    const int m0 = blockIdx.x * 64;

    for (int idx = tid; idx < 64 * 32; idx += 256) {
        int m = idx >> 5, f = idx & 31;
        float4 v = make_float4(0.f, 0.f, 0.f, 0.f);
        int gm = m0 + m;
        if (gm < NN) v = *(const float4*)(A + (size_t)gm * KD + f * 4);
        *(float4*)(As + m * 128 + f * 4) = v;
    }
    for (int idx = tid; idx < 128 * 32; idx += 256) {
        int n = idx & 127, f = idx >> 7;
        float4 v = *(const float4*)(W + (size_t)n * KD + f * 4);
        Bs[(f * 4 + 0) * 128 + n] = v.x;
        Bs[(f * 4 + 1) * 128 + n] = v.y;
        Bs[(f * 4 + 2) * 128 + n] = v.z;
        Bs[(f * 4 + 3) * 128 + n] = v.w;
    }
    __syncthreads();

    unsigned long long acc[4][4];
#pragma unroll
    for (int i = 0; i < 4; i++)
#pragma unroll
        for (int j = 0; j < 4; j++) acc[i][j] = 0ULL;

#pragma unroll 4
    for (int kk = 0; kk < 128; kk++) {
        const float* ar = As + (ty * 8) * 128 + kk;   // broadcast reads
        unsigned long long ap[4];
#pragma unroll
        for (int i = 0; i < 4; i++)
            ap[i] = pk2(ar[(2 * i) * 128], ar[(2 * i + 1) * 128]);
        float4 b = *(const float4*)(Bs + kk * 128 + tx * 4);
        unsigned long long bd[4];
        bd[0] = pk2(b.x, b.x); bd[1] = pk2(b.y, b.y);
        bd[2] = pk2(b.z, b.z); bd[3] = pk2(b.w, b.w);
#pragma unroll
        for (int i = 0; i < 4; i++)
#pragma unroll
            for (int j = 0; j < 4; j++)
                ffma2(acc[i][j], ap[i], bd[j]);
    }

    float bj[4];
#pragma unroll
    for (int j = 0; j < 4; j++) bj[j] = bias[tx * 4 + j];

#pragma unroll
    for (int mp = 0; mp < 4; mp++) {
        float lo[4], hi[4];
#pragma unroll
        for (int j = 0; j < 4; j++) up2(acc[mp][j], lo[j], hi[j]);
        int r0 = m0 + ty * 8 + mp * 2;
        if (r0 < NN) {
            __half2 ha = __floats2half2_rn(lo[0] + bj[0], lo[1] + bj[1]);
            __half2 hb = __floats2half2_rn(lo[2] + bj[2], lo[3] + bj[3]);
            uint2 pv = make_uint2(*(unsigned*)&ha, *(unsigned*)&hb);
            *(uint2*)(C + (size_t)r0 * KD + tx * 4) = pv;
        }
        if (r0 + 1 < NN) {
            __half2 ha = __floats2half2_rn(hi[0] + bj[0], hi[1] + bj[1]);
            __half2 hb = __floats2half2_rn(hi[2] + bj[2], hi[3] + bj[3]);
            uint2 pv = make_uint2(*(unsigned*)&ha, *(unsigned*)&hb);
            *(uint2*)(C + (size_t)(r0 + 1) * KD + tx * 4) = pv;
        }
    }
}

// ---------------- GEMM2: H2h[M,64] = fp16( A1[M,128]*W2[64,128]^T + b2 ) ----
// BM=64, 64KB smem -> 3 CTAs/SM. tx=tid&15: 4 n-cols; ty=tid>>4: 4 m-rows.
__global__ __launch_bounds__(256, 3)
void k_gemm2(const float* __restrict__ A, const float* __restrict__ W,
             const float* __restrict__ bias, __half* __restrict__ C) {
    extern __shared__ float sm[];
    float* As = sm;              // [64][128]
    float* Bs = sm + 64 * 128;   // [128 k][64 n]
    const int tid = threadIdx.x;
    const int tx = tid & 15, ty = tid >> 4;
    const int m0 = blockIdx.x * 64;

    for (int idx = tid; idx < 64 * 32; idx += 256) {
        int m = idx >> 5, f = idx & 31;
        float4 v = make_float4(0.f, 0.f, 0.f, 0.f);
        int gm = m0 + m;
        if (gm < NN) v = *(const float4*)(A + (size_t)gm * KD + f * 4);
        *(float4*)(As + m * 128 + f * 4) = v;
    }
    for (int idx = tid; idx < 64 * 32; idx += 256) {
        int n = idx & 63, f = idx >> 6;
        float4 v = *(const float4*)(W + (size_t)n * KD + f * 4);
        Bs[(f * 4 + 0) * 64 + n] = v.x;
        Bs[(f * 4 + 1) * 64 + n] = v.y;
        Bs[(f * 4 + 2) * 64 + n] = v.z;
        Bs[(f * 4 + 3) * 64 + n] = v.w;
    }
    __syncthreads();

    unsigned long long acc[2][4];
#pragma unroll
    for (int i = 0; i < 2; i++)
#pragma unroll
        for (int j = 0; j < 4; j++) acc[i][j] = 0ULL;

#pragma unroll 4
    for (int kk = 0; kk < 128; kk++) {
        const float* ar = As + (ty * 4) * 128 + kk;
        unsigned long long ap[2];
        ap[0] = pk2(ar[0], ar[128]);
        ap[1] = pk2(ar[256], ar[384]);
        float4 b = *(const float4*)(Bs + kk * 64 + tx * 4);
        unsigned long long bd[4];
        bd[0] = pk2(b.x, b.x); bd[1] = pk2(b.y, b.y);
        bd[2] = pk2(b.z, b.z); bd[3] = pk2(b.w, b.w);
#pragma unroll
        for (int i = 0; i < 2; i++)
#pragma unroll
            for (int j = 0; j < 4; j++)
                ffma2(acc[i][j], ap[i], bd[j]);
    }

    float bj[4];
#pragma unroll
    for (int j = 0; j < 4; j++) bj[j] = bias[tx * 4 + j];

#pragma unroll
    for (int mp = 0; mp < 2; mp++) {
        float lo[4], hi[4];
#pragma unroll
        for (int j = 0; j < 4; j++) up2(acc[mp][j], lo[j], hi[j]);
        int r0 = m0 + ty * 4 + mp * 2;
        if (r0 < NN) {
            __half2 ha = __floats2half2_rn(lo[0] + bj[0], lo[1] + bj[1]);
            __half2 hb = __floats2half2_rn(lo[2] + bj[2], lo[3] + bj[3]);
            uint2 pv = make_uint2(*(unsigned*)&ha, *(unsigned*)&hb);
            *(uint2*)(C + (size_t)r0 * OC + tx * 4) = pv;
        }
        if (r0 + 1 < NN) {
            __half2 ha = __floats2half2_rn(hi[0] + bj[0], hi[1] + bj[1]);
            __half2 hb = __floats2half2_rn(hi[2] + bj[2], hi[3] + bj[3]);
            uint2 pv = make_uint2(*(unsigned*)&ha, *(unsigned*)&hb);
            *(uint2*)(C + (size_t)(r0 + 1) * OC + tx * 4) = pv;
        }
    }
}

// ---------------- CSR gather (warp per node, fp16 src, fp32 accumulate) -----
// A1[v] = relu( 1/(deg+1) * (H1[v] + sum_u H1[u]) ), 128 feats, 8B/lane
__global__ __launch_bounds__(256) void k_gather1() {
    int v = blockIdx.x * 8 + (threadIdx.x >> 5);
    if (v >= NN) return;
    int lane = threadIdx.x & 31;
    const uint2* __restrict__ H = (const uint2*)g_H1h;   // row = 32 uint2
    int deg = g_cur1[v] - v * CAP;
    const int* __restrict__ src = g_csr1 + v * CAP;

    uint2 ps = H[(size_t)v * 32 + lane];
    float2 s0 = __half22float2(*(__half2*)&ps.x);
    float2 s1 = __half22float2(*(__half2*)&ps.y);
    float4 a0 = make_float4(s0.x, s0.y, s1.x, s1.y);
    float4 a1 = make_float4(0.f, 0.f, 0.f, 0.f);
    int j = 0;
    while (j < deg) {
        int cnt = deg - j; if (cnt > 32) cnt = 32;
        int u = (lane < cnt) ? src[j + lane] : 0;
        int k = 0;
        for (; k + 2 <= cnt; k += 2) {
            int u0 = __shfl_sync(0xffffffffu, u, k);
            int u1 = __shfl_sync(0xffffffffu, u, k + 1);
            uint2 p0 = H[(size_t)u0 * 32 + lane];
            uint2 p1 = H[(size_t)u1 * 32 + lane];
            float2 x0 = __half22float2(*(__half2*)&p0.x);
            float2 x1 = __half22float2(*(__half2*)&p0.y);
            float2 y0 = __half22float2(*(__half2*)&p1.x);
            float2 y1 = __half22float2(*(__half2*)&p1.y);
            a0.x += x0.x; a0.y += x0.y; a0.z += x1.x; a0.w += x1.y;
            a1.x += y0.x; a1.y += y0.y; a1.z += y1.x; a1.w += y1.y;
        }
        if (k < cnt) {
            int u0 = __shfl_sync(0xffffffffu, u, k);
            uint2 p0 = H[(size_t)u0 * 32 + lane];
            float2 x0 = __half22float2(*(__half2*)&p0.x);
            float2 x1 = __half22float2(*(__half2*)&p0.y);
            a0.x += x0.x; a0.y += x0.y; a0.z += x1.x; a0.w += x1.y;
        }
        j += cnt;
    }
    float n = 1.0f / (float)(deg + 1);
    float4 o;
    o.x = fmaxf(n * (a0.x + a1.x), 0.f);
    o.y = fmaxf(n * (a0.y + a1.y), 0.f);
    o.z = fmaxf(n * (a0.z + a1.z), 0.f);
    o.w = fmaxf(n * (a0.w + a1.w), 0.f);
    ((float4*)g_A1)[(size_t)v * 32 + lane] = o;
}

// out[v] = 1/(deg+1) * (H2[v] + sum H2[u]), 64 feats, 4B/lane (half2)
__global__ __launch_bounds__(256) void k_gather2(float* __restrict__ out) {
    int v = blockIdx.x * 8 + (threadIdx.x >> 5);
    if (v >= NN) return;
    int lane = threadIdx.x & 31;
    const __half2* __restrict__ H = (const __half2*)g_H2h;  // row = 32 half2
    int deg = g_cur2[v] - v * CAP;
    const int* __restrict__ src = g_csr2 + v * CAP;

    float2 a0 = __half22float2(H[(size_t)v * 32 + lane]);
    float2 a1 = make_float2(0.f, 0.f);
    int j = 0;
    while (j < deg) {
        int cnt = deg - j; if (cnt > 32) cnt = 32;
        int u = (lane < cnt) ? src[j + lane] : 0;
        int k = 0;
        for (; k + 2 <= cnt; k += 2) {
            int u0 = __shfl_sync(0xffffffffu, u, k);
            int u1 = __shfl_sync(0xffffffffu, u, k + 1);
            float2 x0 = __half22float2(H[(size_t)u0 * 32 + lane]);
            float2 x1 = __half22float2(H[(size_t)u1 * 32 + lane]);
            a0.x += x0.x; a0.y += x0.y;
            a1.x += x1.x; a1.y += x1.y;
        }
        if (k < cnt) {
            int u0 = __shfl_sync(0xffffffffu, u, k);
            float2 x0 = __half22float2(H[(size_t)u0 * 32 + lane]);
            a0.x += x0.x; a0.y += x0.y;
        }
        j += cnt;
    }
    float n = 1.0f / (float)(deg + 1);
    float2 o;
    o.x = n * (a0.x + a1.x);
    o.y = n * (a0.y + a1.y);
    ((float2*)out)[(size_t)v * 32 + lane] = o;
}

// ---------------- launch -----------------------------------------------------
extern "C" void kernel_launch(void* const* d_in, const int* in_sizes, int n_in,
                              void* d_out, int out_size) {
    const float* x  = (const float*)d_in[0];
    const int*   ei = (const int*)d_in[1];
    const float* W1 = (const float*)d_in[2];
    const float* b1 = (const float*)d_in[3];
    const float* W2 = (const float*)d_in[4];
    const float* b2 = (const float*)d_in[5];
    float* out = (float*)d_out;

    __half *pH1h, *pH2h; float* pA1;
    cudaGetSymbolAddress((void**)&pH1h, g_H1h);
    cudaGetSymbolAddress((void**)&pA1,  g_A1);
    cudaGetSymbolAddress((void**)&pH2h, g_H2h);

    cudaFuncSetAttribute(k_gemm1, cudaFuncAttributeMaxDynamicSharedMemorySize, 98304);
    cudaFuncSetAttribute(k_gemm2, cudaFuncAttributeMaxDynamicSharedMemorySize, 65536);

    // bucket-CSR build
    k_init<<<(NN + 255) / 256, 256>>>();
    k_fill<<<(EE + 255) / 256, 256>>>(ei);

    // layer 1
    k_gemm1<<<(NN + 63) / 64, 256, 98304>>>(x, W1, b1, pH1h);
    k_gather1<<<(NN + 7) / 8, 256>>>();

    // layer 2
    k_gemm2<<<(NN + 63) / 64, 256, 65536>>>(pA1, W2, b2, pH2h);
    k_gather2<<<(NN + 7) / 8, 256>>>(out);
}

// round 7
// speedup vs baseline: 2.0443x; 1.6043x over previous
#include <cuda_runtime.h>
#include <cuda_fp16.h>
#include <cstdint>

#define NN 50000
#define EE 800000
#define KD 128      // IN_C == HID_C
#define OC 64       // OUT_C
#define CAP 96      // per-node CSR bucket capacity (deg ~ Poisson(16))
#define LDH 136     // padded smem row length in halves (conflict-free)

// ---------------- scratch (device globals; no allocation allowed) ----------
__device__ __align__(16) __half g_H1h[NN * KD];  // fp16 X*W1^T+b1
__device__ __align__(16) __half g_A1h[NN * KD];  // fp16 relu(aggregated)
__device__ __align__(16) __half g_H2h[NN * OC];  // fp16 A1*W2^T+b2
__device__ int g_cur1[NN], g_cur2[NN];
__device__ int g_csr1[NN * CAP], g_csr2[NN * CAP];

// ---------------- bucket-CSR build ------------------------------------------
__global__ void k_init() {
    int i = blockIdx.x * blockDim.x + threadIdx.x;
    if (i < NN) { g_cur1[i] = i * CAP; g_cur2[i] = i * CAP; }
}

__global__ __launch_bounds__(256) void k_fill(const int* __restrict__ ei) {
    int e = blockIdx.x * blockDim.x + threadIdx.x;
    if (e >= EE) return;
    int r = ei[e], c = ei[EE + e];
    int p1 = atomicAdd(&g_cur1[c], 1);
    g_csr1[p1] = r;
    int p2 = atomicAdd(&g_cur2[r], 1);
    g_csr2[p2] = c;
}

// ---------------- HMMA GEMM: C[M,BN] = fp16( A[M,128]*W[BN,128]^T + b ) -----
// 128-row CTA tile, 8 warps = 4(m) x 2(n); warp tile 32 x BN/2.
// mma.sync m16n8k16 f32.f16.f16.f32; fragments via plain LDS.32 from padded smem.
template<int BN, bool AHALF>
__global__ __launch_bounds__(256)
void k_gemm(const void* __restrict__ Ain, const float* __restrict__ W,
            const float* __restrict__ bias, __half* __restrict__ C) {
    extern __shared__ __half sh[];
    __half* As = sh;              // [128][LDH]
    __half* Bs = sh + 128 * LDH;  // [BN][LDH]
    const int tid = threadIdx.x, wid = tid >> 5, lane = tid & 31;
    const int m0 = blockIdx.x * 128;

    // stage A
    if (AHALF) {
        const __half* A = (const __half*)Ain;
        for (int idx = tid; idx < 128 * 16; idx += 256) {   // 16B chunks
            int m = idx >> 4, q = idx & 15;
            uint4 v = make_uint4(0u, 0u, 0u, 0u);
            if (m0 + m < NN) v = *(const uint4*)(A + (size_t)(m0 + m) * KD + q * 8);
            *(uint4*)(As + m * LDH + q * 8) = v;
        }
    } else {
        const float* A = (const float*)Ain;
        for (int idx = tid; idx < 128 * 32; idx += 256) {
            int m = idx >> 5, f = idx & 31;
            float4 v = make_float4(0.f, 0.f, 0.f, 0.f);
            if (m0 + m < NN) v = *(const float4*)(A + (size_t)(m0 + m) * KD + f * 4);
            __half2 h0 = __floats2half2_rn(v.x, v.y);
            __half2 h1 = __floats2half2_rn(v.z, v.w);
            *(uint2*)(As + m * LDH + f * 4) =
                make_uint2(*(uint32_t*)&h0, *(uint32_t*)&h1);
        }
    }
    // stage B: W[BN][128] fp32 -> fp16 rows (n-major == col-major B fragment)
    for (int idx = tid; idx < BN * 32; idx += 256) {
        int n = idx >> 5, f = idx & 31;
        float4 v = *(const float4*)(W + (size_t)n * KD + f * 4);
        __half2 h0 = __floats2half2_rn(v.x, v.y);
        __half2 h1 = __floats2half2_rn(v.z, v.w);
        *(uint2*)(Bs + n * LDH + f * 4) =
            make_uint2(*(uint32_t*)&h0, *(uint32_t*)&h1);
    }
    __syncthreads();

    constexpr int NW = BN / 16;          // n sub-tiles (8x wide) per warp
    const int mw = (wid & 3) * 32;
    const int nw = (wid >> 2) * (BN / 2);
    const int g = lane >> 2, q4 = lane & 3;

    float acc[2][NW][4];
#pragma unroll
    for (int mi = 0; mi < 2; mi++)
#pragma unroll
        for (int nj = 0; nj < NW; nj++)
#pragma unroll
            for (int c = 0; c < 4; c++) acc[mi][nj][c] = 0.f;

#pragma unroll
    for (int ks = 0; ks < 8; ks++) {
        const int k2 = ks * 16 + q4 * 2;
        uint32_t a[2][4];
#pragma unroll
        for (int mi = 0; mi < 2; mi++) {
            const __half* ap = As + (mw + mi * 16 + g) * LDH;
            a[mi][0] = *(const uint32_t*)(ap + k2);
            a[mi][1] = *(const uint32_t*)(ap + 8 * LDH + k2);
            a[mi][2] = *(const uint32_t*)(ap + k2 + 8);
            a[mi][3] = *(const uint32_t*)(ap + 8 * LDH + k2 + 8);
        }
#pragma unroll
        for (int nj = 0; nj < NW; nj++) {
            const __half* bp = Bs + (nw + nj * 8 + g) * LDH;
            uint32_t b0 = *(const uint32_t*)(bp + k2);
            uint32_t b1 = *(const uint32_t*)(bp + k2 + 8);
#pragma unroll
            for (int mi = 0; mi < 2; mi++) {
                asm volatile(
                    "mma.sync.aligned.m16n8k16.row.col.f32.f16.f16.f32 "
                    "{%0,%1,%2,%3}, {%4,%5,%6,%7}, {%8,%9}, {%0,%1,%2,%3};"
                    : "+f"(acc[mi][nj][0]), "+f"(acc[mi][nj][1]),
                      "+f"(acc[mi][nj][2]), "+f"(acc[mi][nj][3])
                    : "r"(a[mi][0]), "r"(a[mi][1]), "r"(a[mi][2]), "r"(a[mi][3]),
                      "r"(b0), "r"(b1));
            }
        }
    }

    float2 bv[NW];
#pragma unroll
    for (int nj = 0; nj < NW; nj++) {
        int c0 = nw + nj * 8 + q4 * 2;
        bv[nj] = make_float2(bias[c0], bias[c0 + 1]);
    }
#pragma unroll
    for (int mi = 0; mi < 2; mi++) {
        int r0 = m0 + mw + mi * 16 + g;
        int r1 = r0 + 8;
#pragma unroll
        for (int nj = 0; nj < NW; nj++) {
            int c0 = nw + nj * 8 + q4 * 2;
            if (r0 < NN) {
                __half2 h = __floats2half2_rn(acc[mi][nj][0] + bv[nj].x,
                                              acc[mi][nj][1] + bv[nj].y);
                *(__half2*)(C + (size_t)r0 * BN + c0) = h;
            }
            if (r1 < NN) {
                __half2 h = __floats2half2_rn(acc[mi][nj][2] + bv[nj].x,
                                              acc[mi][nj][3] + bv[nj].y);
                *(__half2*)(C + (size_t)r1 * BN + c0) = h;
            }
        }
    }
}

// ---------------- CSR gather (warp per node, fp16 src, fp32 accumulate) -----
__global__ __launch_bounds__(256) void k_gather1() {
    int v = blockIdx.x * 8 + (threadIdx.x >> 5);
    if (v >= NN) return;
    int lane = threadIdx.x & 31;
    const uint2* __restrict__ H = (const uint2*)g_H1h;
    int deg = g_cur1[v] - v * CAP;
    const int* __restrict__ src = g_csr1 + v * CAP;

    uint2 ps = H[(size_t)v * 32 + lane];
    float2 s0 = __half22float2(*(__half2*)&ps.x);
    float2 s1 = __half22float2(*(__half2*)&ps.y);
    float4 a0 = make_float4(s0.x, s0.y, s1.x, s1.y);
    float4 a1 = make_float4(0.f, 0.f, 0.f, 0.f);
    int j = 0;
    while (j < deg) {
        int cnt = deg - j; if (cnt > 32) cnt = 32;
        int u = (lane < cnt) ? src[j + lane] : 0;
        int k = 0;
        for (; k + 2 <= cnt; k += 2) {
            int u0 = __shfl_sync(0xffffffffu, u, k);
            int u1 = __shfl_sync(0xffffffffu, u, k + 1);
            uint2 p0 = H[(size_t)u0 * 32 + lane];
            uint2 p1 = H[(size_t)u1 * 32 + lane];
            float2 x0 = __half22float2(*(__half2*)&p0.x);
            float2 x1 = __half22float2(*(__half2*)&p0.y);
            float2 y0 = __half22float2(*(__half2*)&p1.x);
            float2 y1 = __half22float2(*(__half2*)&p1.y);
            a0.x += x0.x; a0.y += x0.y; a0.z += x1.x; a0.w += x1.y;
            a1.x += y0.x; a1.y += y0.y; a1.z += y1.x; a1.w += y1.y;
        }
        if (k < cnt) {
            int u0 = __shfl_sync(0xffffffffu, u, k);
            uint2 p0 = H[(size_t)u0 * 32 + lane];
            float2 x0 = __half22float2(*(__half2*)&p0.x);
            float2 x1 = __half22float2(*(__half2*)&p0.y);
            a0.x += x0.x; a0.y += x0.y; a0.z += x1.x; a0.w += x1.y;
        }
        j += cnt;
    }
    float n = 1.0f / (float)(deg + 1);
    __half2 h0 = __floats2half2_rn(fmaxf(n * (a0.x + a1.x), 0.f),
                                   fmaxf(n * (a0.y + a1.y), 0.f));
    __half2 h1 = __floats2half2_rn(fmaxf(n * (a0.z + a1.z), 0.f),
                                   fmaxf(n * (a0.w + a1.w), 0.f));
    ((uint2*)g_A1h)[(size_t)v * 32 + lane] =
        make_uint2(*(uint32_t*)&h0, *(uint32_t*)&h1);
}

__global__ __launch_bounds__(256) void k_gather2(float* __restrict__ out) {
    int v = blockIdx.x * 8 + (threadIdx.x >> 5);
    if (v >= NN) return;
    int lane = threadIdx.x & 31;
    const __half2* __restrict__ H = (const __half2*)g_H2h;
    int deg = g_cur2[v] - v * CAP;
    const int* __restrict__ src = g_csr2 + v * CAP;

    float2 a0 = __half22float2(H[(size_t)v * 32 + lane]);
    float2 a1 = make_float2(0.f, 0.f);
    int j = 0;
    while (j < deg) {
        int cnt = deg - j; if (cnt > 32) cnt = 32;
        int u = (lane < cnt) ? src[j + lane] : 0;
        int k = 0;
        for (; k + 2 <= cnt; k += 2) {
            int u0 = __shfl_sync(0xffffffffu, u, k);
            int u1 = __shfl_sync(0xffffffffu, u, k + 1);
            float2 x0 = __half22float2(H[(size_t)u0 * 32 + lane]);
            float2 x1 = __half22float2(H[(size_t)u1 * 32 + lane]);
            a0.x += x0.x; a0.y += x0.y;
            a1.x += x1.x; a1.y += x1.y;
        }
        if (k < cnt) {
            int u0 = __shfl_sync(0xffffffffu, u, k);
            float2 x0 = __half22float2(H[(size_t)u0 * 32 + lane]);
            a0.x += x0.x; a0.y += x0.y;
        }
        j += cnt;
    }
    float n = 1.0f / (float)(deg + 1);
    float2 o;
    o.x = n * (a0.x + a1.x);
    o.y = n * (a0.y + a1.y);
    ((float2*)out)[(size_t)v * 32 + lane] = o;
}

// ---------------- launch -----------------------------------------------------
extern "C" void kernel_launch(void* const* d_in, const int* in_sizes, int n_in,
                              void* d_out, int out_size) {
    const float* x  = (const float*)d_in[0];
    const int*   ei = (const int*)d_in[1];
    const float* W1 = (const float*)d_in[2];
    const float* b1 = (const float*)d_in[3];
    const float* W2 = (const float*)d_in[4];
    const float* b2 = (const float*)d_in[5];
    float* out = (float*)d_out;

    __half *pH1h, *pA1h, *pH2h;
    cudaGetSymbolAddress((void**)&pH1h, g_H1h);
    cudaGetSymbolAddress((void**)&pA1h, g_A1h);
    cudaGetSymbolAddress((void**)&pH2h, g_H2h);

    const int smem1 = (128 + 128) * LDH * 2;   // 69632
    const int smem2 = (128 + 64) * LDH * 2;    // 52224
    cudaFuncSetAttribute((const void*)k_gemm<128, false>,
                         cudaFuncAttributeMaxDynamicSharedMemorySize, smem1);
    cudaFuncSetAttribute((const void*)k_gemm<64, true>,
                         cudaFuncAttributeMaxDynamicSharedMemorySize, smem2);

    // bucket-CSR build
    k_init<<<(NN + 255) / 256, 256>>>();
    k_fill<<<(EE + 255) / 256, 256>>>(ei);

    // layer 1
    k_gemm<128, false><<<(NN + 127) / 128, 256, smem1>>>(x, W1, b1, pH1h);
    k_gather1<<<(NN + 7) / 8, 256>>>();

    // layer 2
    k_gemm<64, true><<<(NN + 127) / 128, 256, smem2>>>(pA1h, W2, b2, pH2h);
    k_gather2<<<(NN + 7) / 8, 256>>>(out);
}